// round 11
// baseline (speedup 1.0000x reference)
#include <cuda_runtime.h>
#include <math.h>

// ---------------------------------------------------------------------------
// RotatedIoULoss — separable Green's-theorem form in the unit box,
// 2 boxes per thread, straight-line (no divergent guards) for chain
// interleaving.
//
// Coordinates scaled by (1/hw, 1/hh) so box2 = [-1,1]^2. Per edge:
// y-slab window [a,b], x-crossing breakpoints clamped into [a,b],
// 3 trapezoids folded into area2. Out-of-range lanes read benign 1.0-filled
// boxes (iou=1 -> log=0) and get weight 0, so both box computations run
// unconditionally.
// ---------------------------------------------------------------------------

#define IOU_EPS 1e-6f
#define BLOCK 256
#define PERB  (2 * BLOCK)          // boxes per block
#define MAXB  8192

__device__ float g_partial[MAXB];
__device__ unsigned int g_count = 0;   // reset by last block each launch

__device__ __forceinline__ float clamp1(float v) {
    return fminf(fmaxf(v, -1.f), 1.f);
}

__device__ __forceinline__ float box_loss(const float* __restrict__ P,
                                          const float* __restrict__ T,
                                          float w) {
    float px = P[0], py = P[1], pw = P[2], ph = P[3], pa = P[4];
    float qx = T[0], qy = T[1], qw = T[2], qh = T[3], qa = T[4];

    // frame change into box2's local axes
    float cb, sb; __sincosf(qa, &sb, &cb);
    float dxc = px - qx, dyc = py - qy;
    float ox =  dxc * cb + dyc * sb;
    float oy = -dxc * sb + dyc * cb;
    float cr, sr; __sincosf(pa - qa, &sr, &cr);

    float hw = 0.5f * qw, hh = 0.5f * qh;
    float hx = 0.5f * pw, hy = 0.5f * ph;

    // unit-box scaling: one RCP serves both axes (hw,hh >= 0.5 in data)
    float hwh  = hw * hh;
    float ihwh = __fdividef(1.f, hwh);
    float ihw = hh * ihwh, ihh = hw * ihwh;

    float Ox = ox * ihw, Oy = oy * ihh;
    float Ux = (hx * cr) * ihw, Uy = (hx * sr) * ihh;
    float Wx = -(hy * sr) * ihw, Wy = (hy * cr) * ihh;

    // scaled corners (CCW)
    float v0x = Ox + Ux + Wx, v0y = Oy + Uy + Wy;
    float v1x = Ox - Ux + Wx, v1y = Oy - Uy + Wy;
    float v2x = Ox - Ux - Wx, v2y = Oy - Uy - Wy;
    float v3x = Ox + Ux - Wx, v3y = Oy + Uy - Wy;

    // edge dirs: A = v3->v0 = 2W, B = v0->v1 = -2U (C=-A, D=-B)
    float dAx = 2.f * Wx, dAy = 2.f * Wy;
    float dBx = -2.f * Ux, dBy = -2.f * Uy;
    float iAx = __fdividef(1.f, dAx), iAy = __fdividef(1.f, dAy);
    float iBx = __fdividef(1.f, dBx), iBy = __fdividef(1.f, dBy);

    float area2 = 0.f;

#define EDGE(axv, ayv, dx_, dy_, ix_, iy_) do {                        \
        float ta = fmaf((axv), -(ix_), -(ix_));   /* (-1-ax)*ix */     \
        float tb = fmaf((axv), -(ix_),  (ix_));   /* ( 1-ax)*ix */     \
        float tc = fmaf((ayv), -(iy_), -(iy_));                        \
        float td = fmaf((ayv), -(iy_),  (iy_));                        \
        float a_ = __saturatef(fminf(tc, td));                         \
        float b_ = __saturatef(fmaxf(tc, td));                         \
        float t1 = fminf(ta, tb), t2 = fmaxf(ta, tb);                  \
        float c1 = fminf(fmaxf(t1, a_), b_);                           \
        float c2 = fminf(fmaxf(t2, a_), b_);                           \
        float Xa = clamp1(fmaf(a_, (dx_), (axv)));                     \
        float X1 = clamp1(fmaf(c1, (dx_), (axv)));                     \
        float X2 = clamp1(fmaf(c2, (dx_), (axv)));                     \
        float Xb = clamp1(fmaf(b_, (dx_), (axv)));                     \
        float e = Xa * (c1 - a_);                                      \
        e = fmaf(X1, c2 - a_, e);                                      \
        e = fmaf(X2, b_ - c1, e);                                      \
        e = fmaf(Xb, b_ - c2, e);                                      \
        area2 = fmaf((dy_), e, area2);                                 \
    } while (0)

    EDGE(v3x, v3y,  dAx,  dAy,  iAx,  iAy);
    EDGE(v0x, v0y,  dBx,  dBy,  iBx,  iBy);
    EDGE(v1x, v1y, -dAx, -dAy, -iAx, -iAy);
    EDGE(v2x, v2y, -dBx, -dBy, -iBx, -iBy);
#undef EDGE

    float inter = 0.5f * fabsf(area2) * hwh;

    // conservative separation: certain-disjoint -> exact zero (predicated)
    float radx = fabsf(Ux) + fabsf(Wx);
    float rady = fabsf(Uy) + fabsf(Wy);
    bool sep = (fabsf(Ox) > 1.f + radx) || (fabsf(Oy) > 1.f + rady);
    inter = sep ? 0.f : inter;

    float a1 = pw * ph, a2 = qw * qh;
    float iou = __fdividef(inter, a1 + a2 - inter);
    iou = fmaxf(iou, IOU_EPS);
    return -__logf(iou) * w;
}

__global__ void __launch_bounds__(BLOCK, 6)
rl_main(const float* __restrict__ pred,
        const float* __restrict__ target,
        const float* __restrict__ weight,
        float* __restrict__ out,
        int n, int nb, float inv_n) {
    // ---- coalesced float4 staging of stride-5 rows (PERB boxes) ----
    __shared__ float4 sp4[PERB * 5 / 4];
    __shared__ float4 st4[PERB * 5 / 4];
    float* sp = (float*)sp4;
    float* st = (float*)st4;
    int bbase = blockIdx.x * PERB;
    int gbase = bbase * 5;
    int limit = n * 5 - gbase;
    const float4* p4 = (const float4*)(pred + gbase);
    const float4* t4 = (const float4*)(target + gbase);
    if (limit >= PERB * 5) {
        // fast path: full block, no bounds checks
#pragma unroll
        for (int j = threadIdx.x; j < PERB * 5 / 4; j += BLOCK) {
            sp4[j] = p4[j];
            st4[j] = t4[j];
        }
    } else {
        // boundary block: benign 1.0 fill (box (1,1,1,1,1) -> iou=1 -> 0 loss)
        for (int j = threadIdx.x; j < PERB * 5 / 4; j += BLOCK) {
            float4 vp = make_float4(1.f, 1.f, 1.f, 1.f);
            float4 vt = vp;
            int e0 = j * 4;
            if (e0 + 3 < limit) {
                vp = p4[j]; vt = t4[j];
            } else if (e0 < limit) {
                const float* ps = pred + gbase;
                const float* ts = target + gbase;
                float* vpf = &vp.x; float* vtf = &vt.x;
                for (int c = 0; c < 4; c++)
                    if (e0 + c < limit) { vpf[c] = ps[e0 + c]; vtf[c] = ts[e0 + c]; }
            }
            sp4[j] = vp; st4[j] = vt;
        }
    }
    __syncthreads();

    int i0 = bbase + threadIdx.x;
    int i1 = i0 + BLOCK;
    // predicated weights (0 for OOB lanes); box data is benign for OOB
    float w0 = (i0 < n) ? weight[i0] : 0.f;
    float w1 = (i1 < n) ? weight[i1] : 0.f;

    // unconditional: two independent chains, fully interleavable
    float loss = box_loss(sp + threadIdx.x * 5, st + threadIdx.x * 5, w0)
               + box_loss(sp + (threadIdx.x + BLOCK) * 5,
                          st + (threadIdx.x + BLOCK) * 5, w1);

    // ---- block reduction -> per-block partial ----
    unsigned mask = 0xFFFFFFFFu;
#pragma unroll
    for (int o = 16; o > 0; o >>= 1)
        loss += __shfl_down_sync(mask, loss, o);

    __shared__ float ws[BLOCK / 32];
    int lane = threadIdx.x & 31;
    int wid = threadIdx.x >> 5;
    if (lane == 0) ws[wid] = loss;
    __syncthreads();
    __shared__ bool is_last;
    if (threadIdx.x == 0) {
        float v = 0.f;
#pragma unroll
        for (int w = 0; w < BLOCK / 32; w++) v += ws[w];
        g_partial[blockIdx.x] = v;
        __threadfence();
        unsigned prev = atomicAdd(&g_count, 1u);
        is_last = (prev == (unsigned)(nb - 1));
    }
    __syncthreads();

    // ---- last block: final reduction (deterministic) ----
    if (is_last) {
        double s = 0.0;
        for (int j = threadIdx.x; j < nb; j += BLOCK)
            s += (double)g_partial[j];
#pragma unroll
        for (int o = 16; o > 0; o >>= 1)
            s += __shfl_down_sync(mask, s, o);
        __shared__ double ds[BLOCK / 32];
        if (lane == 0) ds[wid] = s;
        __syncthreads();
        if (threadIdx.x == 0) {
            double v = 0.0;
#pragma unroll
            for (int w = 0; w < BLOCK / 32; w++) v += ds[w];
            out[0] = (float)(v * (double)inv_n);
            g_count = 0;  // reset for next graph replay
        }
    }
}

extern "C" void kernel_launch(void* const* d_in, const int* in_sizes, int n_in,
                              void* d_out, int out_size) {
    const float* pred   = (const float*)d_in[0];
    const float* target = (const float*)d_in[1];
    const float* weight = (const float*)d_in[2];
    float* out = (float*)d_out;
    int n = in_sizes[2];

    int grid = (n + PERB - 1) / PERB;
    if (grid > MAXB) grid = MAXB;  // n = 1e6 -> 1954 blocks
    rl_main<<<grid, BLOCK>>>(pred, target, weight, out, n, grid,
                             1.0f / (float)n);
}

// round 12
// speedup vs baseline: 1.0135x; 1.0135x over previous
#include <cuda_runtime.h>
#include <math.h>

// ---------------------------------------------------------------------------
// RotatedIoULoss — separable Green's-theorem form in the unit box.
// 2 ADJACENT boxes per thread: their 10 floats = five aligned float2 loads
// per input array + one float2 weight load. No shared-memory staging.
//
// Coordinates scaled by (1/hw, 1/hh) so box2 = [-1,1]^2. Per edge:
// y-slab window [a,b], x-crossing breakpoints clamped into [a,b],
// 3 trapezoids folded into area2. Degenerate (axis-parallel) edges resolve
// through +/-inf under fmin/fmax/saturate semantics.
// ---------------------------------------------------------------------------

#define IOU_EPS 1e-6f
#define BLOCK 128
#define MAXB  8192

__device__ float g_partial[MAXB];
__device__ unsigned int g_count = 0;   // reset by last block each launch

__device__ __forceinline__ float clamp1(float v) {
    return fminf(fmaxf(v, -1.f), 1.f);
}

__device__ __forceinline__ float box_loss(
    float px, float py, float pw, float ph, float pa,
    float qx, float qy, float qw, float qh, float qa, float w) {

    // frame change into box2's local axes
    float cb, sb; __sincosf(qa, &sb, &cb);
    float dxc = px - qx, dyc = py - qy;
    float ox =  dxc * cb + dyc * sb;
    float oy = -dxc * sb + dyc * cb;
    float cr, sr; __sincosf(pa - qa, &sr, &cr);

    float hw = 0.5f * qw, hh = 0.5f * qh;
    float hx = 0.5f * pw, hy = 0.5f * ph;

    // unit-box scaling: one RCP serves both axes
    float hwh  = hw * hh;
    float ihwh = __fdividef(1.f, hwh);
    float ihw = hh * ihwh, ihh = hw * ihwh;

    float Ox = ox * ihw, Oy = oy * ihh;
    float Ux = (hx * cr) * ihw, Uy = (hx * sr) * ihh;
    float Wx = -(hy * sr) * ihw, Wy = (hy * cr) * ihh;

    // scaled corners (CCW)
    float v0x = Ox + Ux + Wx, v0y = Oy + Uy + Wy;
    float v1x = Ox - Ux + Wx, v1y = Oy - Uy + Wy;
    float v2x = Ox - Ux - Wx, v2y = Oy - Uy - Wy;
    float v3x = Ox + Ux - Wx, v3y = Oy + Uy - Wy;

    // edge dirs: A = v3->v0 = 2W, B = v0->v1 = -2U (C=-A, D=-B)
    float dAx = 2.f * Wx, dAy = 2.f * Wy;
    float dBx = -2.f * Ux, dBy = -2.f * Uy;
    float iAx = __fdividef(1.f, dAx), iAy = __fdividef(1.f, dAy);
    float iBx = __fdividef(1.f, dBx), iBy = __fdividef(1.f, dBy);

    float area2 = 0.f;

#define EDGE(axv, ayv, dx_, dy_, ix_, iy_) do {                        \
        float ta = fmaf((axv), -(ix_), -(ix_));   /* (-1-ax)*ix */     \
        float tb = fmaf((axv), -(ix_),  (ix_));   /* ( 1-ax)*ix */     \
        float tc = fmaf((ayv), -(iy_), -(iy_));                        \
        float td = fmaf((ayv), -(iy_),  (iy_));                        \
        float a_ = __saturatef(fminf(tc, td));                         \
        float b_ = __saturatef(fmaxf(tc, td));                         \
        float t1 = fminf(ta, tb), t2 = fmaxf(ta, tb);                  \
        float c1 = fminf(fmaxf(t1, a_), b_);                           \
        float c2 = fminf(fmaxf(t2, a_), b_);                           \
        float Xa = clamp1(fmaf(a_, (dx_), (axv)));                     \
        float X1 = clamp1(fmaf(c1, (dx_), (axv)));                     \
        float X2 = clamp1(fmaf(c2, (dx_), (axv)));                     \
        float Xb = clamp1(fmaf(b_, (dx_), (axv)));                     \
        float e = Xa * (c1 - a_);                                      \
        e = fmaf(X1, c2 - a_, e);                                      \
        e = fmaf(X2, b_ - c1, e);                                      \
        e = fmaf(Xb, b_ - c2, e);                                      \
        area2 = fmaf((dy_), e, area2);                                 \
    } while (0)

    EDGE(v3x, v3y,  dAx,  dAy,  iAx,  iAy);
    EDGE(v0x, v0y,  dBx,  dBy,  iBx,  iBy);
    EDGE(v1x, v1y, -dAx, -dAy, -iAx, -iAy);
    EDGE(v2x, v2y, -dBx, -dBy, -iBx, -iBy);
#undef EDGE

    float inter = 0.5f * fabsf(area2) * hwh;

    // conservative separation: certain-disjoint -> exact zero (predicated)
    float radx = fabsf(Ux) + fabsf(Wx);
    float rady = fabsf(Uy) + fabsf(Wy);
    bool sep = (fabsf(Ox) > 1.f + radx) || (fabsf(Oy) > 1.f + rady);
    inter = sep ? 0.f : inter;

    float a1 = pw * ph, a2 = qw * qh;
    float iou = __fdividef(inter, a1 + a2 - inter);
    iou = fmaxf(iou, IOU_EPS);
    return -__logf(iou) * w;
}

__global__ void __launch_bounds__(BLOCK, 10)
rl_main(const float* __restrict__ pred,
        const float* __restrict__ target,
        const float* __restrict__ weight,
        float* __restrict__ out,
        int n, int nb, float inv_n) {
    int Tid = blockIdx.x * BLOCK + threadIdx.x;   // pair index
    int i0 = 2 * Tid;                              // first box of the pair

    // dummy defaults: iou=1 -> loss contribution 0 with weight 0
    float p0x = 0.f, p0y = 0.f, p0w = 1.f, p0h = 1.f, p0a = 0.f;
    float p1x = 0.f, p1y = 0.f, p1w = 1.f, p1h = 1.f, p1a = 0.f;
    float q0x = 0.f, q0y = 0.f, q0w = 1.f, q0h = 1.f, q0a = 0.f;
    float q1x = 0.f, q1y = 0.f, q1w = 1.f, q1h = 1.f, q1a = 0.f;
    float w0 = 0.f, w1 = 0.f;

    if (i0 + 1 < n) {
        // five aligned float2 loads per array cover both boxes exactly
        const float2* p2 = (const float2*)(pred)   + (size_t)Tid * 5;
        const float2* t2 = (const float2*)(target) + (size_t)Tid * 5;
        float2 a0 = p2[0], a1 = p2[1], a2 = p2[2], a3 = p2[3], a4 = p2[4];
        float2 b0 = t2[0], b1 = t2[1], b2 = t2[2], b3 = t2[3], b4 = t2[4];
        float2 ww = ((const float2*)weight)[Tid];
        // layout: [x0 y0][w0 h0][a0 x1][y1 w1][h1 a1]
        p0x = a0.x; p0y = a0.y; p0w = a1.x; p0h = a1.y; p0a = a2.x;
        p1x = a2.y; p1y = a3.x; p1w = a3.y; p1h = a4.x; p1a = a4.y;
        q0x = b0.x; q0y = b0.y; q0w = b1.x; q0h = b1.y; q0a = b2.x;
        q1x = b2.y; q1y = b3.x; q1w = b3.y; q1h = b4.x; q1a = b4.y;
        w0 = ww.x; w1 = ww.y;
    } else if (i0 < n) {
        // odd tail (n odd): single box
        const float* P = pred + (size_t)i0 * 5;
        const float* T = target + (size_t)i0 * 5;
        p0x = P[0]; p0y = P[1]; p0w = P[2]; p0h = P[3]; p0a = P[4];
        q0x = T[0]; q0y = T[1]; q0w = T[2]; q0h = T[3]; q0a = T[4];
        w0 = weight[i0];
    }

    // two independent chains, fully interleavable
    float loss = box_loss(p0x, p0y, p0w, p0h, p0a,
                          q0x, q0y, q0w, q0h, q0a, w0)
               + box_loss(p1x, p1y, p1w, p1h, p1a,
                          q1x, q1y, q1w, q1h, q1a, w1);

    // ---- block reduction -> per-block partial ----
    unsigned mask = 0xFFFFFFFFu;
#pragma unroll
    for (int o = 16; o > 0; o >>= 1)
        loss += __shfl_down_sync(mask, loss, o);

    __shared__ float ws[BLOCK / 32];
    int lane = threadIdx.x & 31;
    int wid = threadIdx.x >> 5;
    if (lane == 0) ws[wid] = loss;
    __syncthreads();
    __shared__ bool is_last;
    if (threadIdx.x == 0) {
        float v = 0.f;
#pragma unroll
        for (int w = 0; w < BLOCK / 32; w++) v += ws[w];
        g_partial[blockIdx.x] = v;
        __threadfence();
        unsigned prev = atomicAdd(&g_count, 1u);
        is_last = (prev == (unsigned)(nb - 1));
    }
    __syncthreads();

    // ---- last block: final reduction (deterministic) ----
    if (is_last) {
        double s = 0.0;
        for (int j = threadIdx.x; j < nb; j += BLOCK)
            s += (double)g_partial[j];
#pragma unroll
        for (int o = 16; o > 0; o >>= 1)
            s += __shfl_down_sync(mask, s, o);
        __shared__ double ds[BLOCK / 32];
        if (lane == 0) ds[wid] = s;
        __syncthreads();
        if (threadIdx.x == 0) {
            double v = 0.0;
#pragma unroll
            for (int w = 0; w < BLOCK / 32; w++) v += ds[w];
            out[0] = (float)(v * (double)inv_n);
            g_count = 0;  // reset for next graph replay
        }
    }
}

extern "C" void kernel_launch(void* const* d_in, const int* in_sizes, int n_in,
                              void* d_out, int out_size) {
    const float* pred   = (const float*)d_in[0];
    const float* target = (const float*)d_in[1];
    const float* weight = (const float*)d_in[2];
    float* out = (float*)d_out;
    int n = in_sizes[2];

    int pairs = (n + 1) / 2;
    int grid = (pairs + BLOCK - 1) / BLOCK;
    if (grid > MAXB) grid = MAXB;  // n = 1e6 -> 3907 blocks
    rl_main<<<grid, BLOCK>>>(pred, target, weight, out, n, grid,
                             1.0f / (float)n);
}